// round 17
// baseline (speedup 1.0000x reference)
#include <cuda_runtime.h>
#include <cuda_bf16.h>
#include <cuda_fp16.h>
#include <math.h>
#include <cstdint>

#define MAXN 100000
#define MAXE 1600000
#define NBLK 98

// bf16 m16n8k16 mma (sm_80+ PTX)
__device__ __forceinline__ void mma16(float* c,const uint32_t* a,uint32_t b0,uint32_t b1){
    asm volatile("mma.sync.aligned.m16n8k16.row.col.f32.bf16.bf16.f32 "
                 "{%0,%1,%2,%3},{%4,%5,%6,%7},{%8,%9},{%0,%1,%2,%3};"
        :"+f"(c[0]),"+f"(c[1]),"+f"(c[2]),"+f"(c[3])
        :"r"(a[0]),"r"(a[1]),"r"(a[2]),"r"(a[3]),"r"(b0),"r"(b1));
}
// packed split: (x0,x1) -> bf16x2 hi + bf16x2 residual
__device__ __forceinline__ void split2(float x0,float x1,uint32_t&hi,uint32_t&lo){
    __nv_bfloat162 h=__floats2bfloat162_rn(x0,x1);
    hi=reinterpret_cast<uint32_t&>(h);
    float2 f=__bfloat1622float2(h);
    __nv_bfloat162 l=__floats2bfloat162_rn(x0-f.x,x1-f.y);
    lo=reinterpret_cast<uint32_t&>(l);
}
// unpack 4 halves (uint2) -> float4
__device__ __forceinline__ float4 h4(uint2 u){
    __half2 a=*reinterpret_cast<__half2*>(&u.x);
    __half2 b=*reinterpret_cast<__half2*>(&u.y);
    float2 fa=__half22float2(a),fb=__half22float2(b);
    return make_float4(fa.x,fa.y,fb.x,fb.y);
}

__device__ __half g_hh[(size_t)MAXN*128];   // h' fp16 (only h representation)
__device__ float  g_agg[(size_t)MAXN*128];
__device__ float  g_d1[MAXN];
__device__ float  g_d2[MAXN];
__device__ int    g_cnt[MAXN];
__device__ int    g_cur[MAXN];
__device__ int    g_base[MAXN];
__device__ int    g_bsums[NBLK+1];
__device__ float2 g_e1[MAXE];               // CSR slot: {row(bits), g1}
__device__ float2 g_e2[MAXE];               // CSR slot: {row(bits), g2}

__global__ void zero_cnt_kernel(int*cnt,int n){
    int i=blockIdx.x*blockDim.x+threadIdx.x;
    if(i<n) cnt[i]=0;
}
// 4 edges per thread via int4
__global__ void hist_kernel(const int* __restrict__ cols,int* __restrict__ cnt,int E){
    int i=blockIdx.x*blockDim.x+threadIdx.x;
    int i4=i*4;
    if(i4+3<E){
        int4 c=__ldg((const int4*)(cols+i4));
        atomicAdd(cnt+c.x,1);atomicAdd(cnt+c.y,1);
        atomicAdd(cnt+c.z,1);atomicAdd(cnt+c.w,1);
    }else{
        for(int e=i4;e<E;e++) atomicAdd(cnt+__ldg(cols+e),1);
    }
}

// ---------------------------------------------------------------------------
// Gate: bf16 3-term split MMA. Task = 32 edges (2 m-tiles).
__global__ void __launch_bounds__(256) gate_mma_kernel(
    const float* __restrict__ ea,
    const float* __restrict__ m1w1,const float* __restrict__ m1b1,
    const float* __restrict__ m1w2,const float* __restrict__ m1b2,
    const float* __restrict__ m2w1,const float* __restrict__ m2b1,
    const float* __restrict__ m2w2,const float* __restrict__ m2b2,
    const int* __restrict__ rows,const int* __restrict__ cols,
    const int* __restrict__ base,int* __restrict__ cur,
    float2* __restrict__ e1,float2* __restrict__ e2,
    float* __restrict__ deg1,float* __restrict__ deg2,int E)
{
    extern __shared__ float ds[];
    uint32_t* dsu=(uint32_t*)ds;
    float* biasp=ds+4352;
    float* w2p  =ds+4608;
    int tid=threadIdx.x;

    for(int idx=tid;idx<2048;idx+=256){
        int layer=idx>>10,rem=idx&1023,k2=rem>>7,n=rem&127;
        const float* W=layer?m2w1:m1w1;
        float w0=__ldg(W+(2*k2)*128+n),w1=__ldg(W+(2*k2+1)*128+n);
        uint32_t hi,lo; split2(w0,w1,hi,lo);
        dsu[layer*2176+k2*136+n]=hi;
        dsu[layer*2176+1088+k2*136+n]=lo;
    }
    if(tid<256){
        biasp[tid]=(tid<128)?__ldg(m1b1+tid):__ldg(m2b1+tid-128);
        w2p[tid]  =(tid<128)?__ldg(m1w2+tid):__ldg(m2w2+tid-128);
    }
    __syncthreads();

    int lane=tid&31,g=lane>>2,t=lane&3;
    int w=blockIdx.x*(blockDim.x>>5)+(tid>>5);
    int nwarps=gridDim.x*(blockDim.x>>5);
    int ntask=(E+31)>>5;
    float b2v[2]={__ldg(m1b2),__ldg(m2b2)};

    for(int task=w;task<ntask;task+=nwarps){
        int e0=task*32;
        uint32_t Ahi[2][4],Alo[2][4];
        #pragma unroll
        for(int mt=0;mt<2;mt++){
            int r1=e0+mt*16+g,r2=r1+8;
            float2 z=make_float2(0.f,0.f);
            float2 v1a=(r1<E)?*(const float2*)(ea+(size_t)r1*16+2*t):z;
            float2 v1b=(r1<E)?*(const float2*)(ea+(size_t)r1*16+8+2*t):z;
            float2 v2a=(r2<E)?*(const float2*)(ea+(size_t)r2*16+2*t):z;
            float2 v2b=(r2<E)?*(const float2*)(ea+(size_t)r2*16+8+2*t):z;
            split2(v1a.x,v1a.y,Ahi[mt][0],Alo[mt][0]);
            split2(v2a.x,v2a.y,Ahi[mt][1],Alo[mt][1]);
            split2(v1b.x,v1b.y,Ahi[mt][2],Alo[mt][2]);
            split2(v2b.x,v2b.y,Ahi[mt][3],Alo[mt][3]);
        }
        int slotA[2]={-1,-1},slotB[2]={-1,-1};
        #pragma unroll
        for(int layer=0;layer<2;layer++){
            const uint32_t* Bh=dsu+layer*2176;
            const uint32_t* Bl=Bh+1088;
            const float* biasl=biasp+layer*128;
            const float* w2l=w2p+layer*128;
            float p0[2]={0,0},p1[2]={0,0};
            #pragma unroll 2
            for(int nt=0;nt<16;nt++){
                int n0=nt*8;
                float bA=biasl[n0+2*t],bB=biasl[n0+2*t+1];
                float c[2][4];
                #pragma unroll
                for(int mt=0;mt<2;mt++){c[mt][0]=bA;c[mt][1]=bB;c[mt][2]=bA;c[mt][3]=bB;}
                uint32_t b0h=Bh[t*136+n0+g],b1h=Bh[(t+4)*136+n0+g];
                uint32_t b0l=Bl[t*136+n0+g],b1l=Bl[(t+4)*136+n0+g];
                #pragma unroll
                for(int mt=0;mt<2;mt++){
                    mma16(c[mt],Ahi[mt],b0h,b1h);
                    mma16(c[mt],Alo[mt],b0h,b1h);
                    mma16(c[mt],Ahi[mt],b0l,b1l);
                }
                float wA=w2l[n0+2*t],wB=w2l[n0+2*t+1];
                #pragma unroll
                for(int mt=0;mt<2;mt++){
                    p0[mt]+=fmaxf(c[mt][0],0.f)*wA+fmaxf(c[mt][1],0.f)*wB;
                    p1[mt]+=fmaxf(c[mt][2],0.f)*wA+fmaxf(c[mt][3],0.f)*wB;
                }
            }
            #pragma unroll
            for(int mt=0;mt<2;mt++){
                p0[mt]+=__shfl_xor_sync(0xffffffffu,p0[mt],1);
                p0[mt]+=__shfl_xor_sync(0xffffffffu,p0[mt],2);
                p1[mt]+=__shfl_xor_sync(0xffffffffu,p1[mt],1);
                p1[mt]+=__shfl_xor_sync(0xffffffffu,p1[mt],2);
            }
            if(t==0){
                float b2=b2v[layer];
                #pragma unroll
                for(int mt=0;mt<2;mt++){
                    int e=e0+mt*16+g,e2i=e+8;
                    if(layer==0){
                        if(e<E){
                            float gg=1.0f/(1.0f+expf(-(p0[mt]+b2)));
                            int c_=__ldg(cols+e),r_=__ldg(rows+e);
                            int slot=__ldg(base+c_)+atomicAdd(cur+c_,1);
                            slotA[mt]=slot;
                            e1[slot]=make_float2(__int_as_float(r_),gg);
                            atomicAdd(deg1+c_,gg);
                        }
                        if(e2i<E){
                            float gg=1.0f/(1.0f+expf(-(p1[mt]+b2)));
                            int c_=__ldg(cols+e2i),r_=__ldg(rows+e2i);
                            int slot=__ldg(base+c_)+atomicAdd(cur+c_,1);
                            slotB[mt]=slot;
                            e1[slot]=make_float2(__int_as_float(r_),gg);
                            atomicAdd(deg1+c_,gg);
                        }
                    }else{
                        if(slotA[mt]>=0){
                            float gg=1.0f/(1.0f+expf(-(p0[mt]+b2)));
                            int c_=__ldg(cols+e);
                            e2[slotA[mt]]=make_float2(__int_as_float(__ldg(rows+e)),gg);
                            atomicAdd(deg2+c_,gg);
                        }
                        if(slotB[mt]>=0){
                            float gg=1.0f/(1.0f+expf(-(p1[mt]+b2)));
                            int c_=__ldg(cols+e2i);
                            e2[slotB[mt]]=make_float2(__int_as_float(__ldg(rows+e2i)),gg);
                            atomicAdd(deg2+c_,gg);
                        }
                    }
                }
            }
        }
    }
}

// ---------------------------------------------------------------------------
// Dense GEMM: bf16 3-term split; 512 threads; writes fp16 h' scaled by rsqrt(deg).
__global__ void __launch_bounds__(512) gemm_mma_kernel(
    const float* __restrict__ X,const float* __restrict__ W,
    const float* __restrict__ deg,
    __half* __restrict__ hh,int n,int relu_in)
{
    extern __shared__ float sm[];
    uint32_t* Wh=(uint32_t*)sm;
    uint32_t* Wl=Wh+8704;
    float* Xs=sm+17408;
    int tid=threadIdx.x,wid=tid>>5,lane=tid&31;
    int g=lane>>2,t=lane&3;

    for(int idx=tid;idx<8192;idx+=512){
        int k2=idx>>7,nn=idx&127;
        float w0=__ldg(W+(2*k2)*128+nn),w1=__ldg(W+(2*k2+1)*128+nn);
        uint32_t hi,lo; split2(w0,w1,hi,lo);
        Wh[k2*136+nn]=hi; Wl[k2*136+nn]=lo;
    }
    __syncthreads();

    float* Xw=Xs+wid*(16*132);
    int ntiles=(n+255)>>8;
    for(int tile=blockIdx.x;tile<ntiles;tile+=gridDim.x){
        int r0=tile*256+wid*16;
        #pragma unroll 4
        for(int i=0;i<16;i++){
            int r=r0+i;
            float4 v=make_float4(0.f,0.f,0.f,0.f);
            if(r<n) v=__ldg((const float4*)(X+(size_t)r*128)+lane);
            if(relu_in){v.x=fmaxf(v.x,0.f);v.y=fmaxf(v.y,0.f);v.z=fmaxf(v.z,0.f);v.w=fmaxf(v.w,0.f);}
            float* d=Xw+i*132+lane*4;
            d[0]=v.x;d[1]=v.y;d[2]=v.z;d[3]=v.w;
        }
        __syncwarp();

        float c[16][4];
        #pragma unroll
        for(int nf=0;nf<16;nf++){c[nf][0]=0.f;c[nf][1]=0.f;c[nf][2]=0.f;c[nf][3]=0.f;}

        #pragma unroll 1
        for(int ks=0;ks<8;ks++){
            int k0=ks*16,kb=ks*8;
            float2 xa=*(const float2*)(Xw+g*132+k0+2*t);
            float2 xb=*(const float2*)(Xw+(g+8)*132+k0+2*t);
            float2 xc=*(const float2*)(Xw+g*132+k0+8+2*t);
            float2 xd=*(const float2*)(Xw+(g+8)*132+k0+8+2*t);
            uint32_t ahi[4],alo[4];
            split2(xa.x,xa.y,ahi[0],alo[0]);
            split2(xb.x,xb.y,ahi[1],alo[1]);
            split2(xc.x,xc.y,ahi[2],alo[2]);
            split2(xd.x,xd.y,ahi[3],alo[3]);
            #pragma unroll
            for(int nf=0;nf<16;nf++){
                int n0=nf*8;
                uint32_t b0h=Wh[(kb+t)*136+n0+g],b1h=Wh[(kb+t+4)*136+n0+g];
                uint32_t b0l=Wl[(kb+t)*136+n0+g],b1l=Wl[(kb+t+4)*136+n0+g];
                mma16(c[nf],ahi,b0h,b1h);
                mma16(c[nf],alo,b0h,b1h);
                mma16(c[nf],ahi,b0l,b1l);
            }
        }

        int ra=r0+g,rb=r0+g+8;
        float da=(ra<n)?rsqrtf(__ldg(deg+ra)):0.f;
        float db=(rb<n)?rsqrtf(__ldg(deg+rb)):0.f;
        #pragma unroll
        for(int nf=0;nf<16;nf++){
            int col=nf*8+2*t;
            if(ra<n) *(__half2*)(hh+(size_t)ra*128+col)=__floats2half2_rn(c[nf][0]*da,c[nf][1]*da);
            if(rb<n) *(__half2*)(hh+(size_t)rb*128+col)=__floats2half2_rn(c[nf][2]*db,c[nf][3]*db);
        }
        __syncwarp();
    }
}

__global__ void scan_block_sums(const int* __restrict__ cnt,int* __restrict__ bsums,int n){
    __shared__ int wsum[32];
    int i=blockIdx.x*1024+threadIdx.x;
    int v=(i<n)?cnt[i]:0;
    #pragma unroll
    for(int o=16;o;o>>=1) v+=__shfl_down_sync(0xffffffffu,v,o);
    if((threadIdx.x&31)==0) wsum[threadIdx.x>>5]=v;
    __syncthreads();
    if(threadIdx.x<32){
        int s=wsum[threadIdx.x];
        #pragma unroll
        for(int o=16;o;o>>=1) s+=__shfl_down_sync(0xffffffffu,s,o);
        if(threadIdx.x==0) bsums[blockIdx.x]=s;
    }
}
__global__ void scan_final(const int* __restrict__ cnt,const int* __restrict__ bsums,
                           int* __restrict__ base,float* __restrict__ d1,
                           float* __restrict__ d2,int* __restrict__ cur,int n){
    __shared__ int wsum[32];
    __shared__ int boff;
    int tid=threadIdx.x;
    if(tid==0) boff=0;
    __syncthreads();
    if(tid<(int)blockIdx.x) atomicAdd(&boff,__ldg(bsums+tid));
    int i=blockIdx.x*1024+tid;
    int v=(i<n)?cnt[i]:0;
    int lane=tid&31,w=tid>>5;
    int incl=v;
    #pragma unroll
    for(int o=1;o<32;o<<=1){int t=__shfl_up_sync(0xffffffffu,incl,o);if(lane>=o)incl+=t;}
    if(lane==31) wsum[w]=incl;
    __syncthreads();
    if(w==0){
        int s=wsum[lane];
        #pragma unroll
        for(int o=1;o<32;o<<=1){int t=__shfl_up_sync(0xffffffffu,s,o);if(lane>=o)s+=t;}
        __syncwarp();
        wsum[lane]=s;
    }
    __syncthreads();
    int prev=(w==0)?0:wsum[w-1];
    if(i<n){
        base[i]=incl-v+prev+boff;
        d1[i]=1.0f; d2[i]=1.0f; cur[i]=0;
    }
}

// ---------------------------------------------------------------------------
// Gather: warp per node, half-warps own alternating edges, LDG.128 rows.
// out[i] = rsqrt(deg[i])*( hh[i] + sum g[s]*hh[row[s]] )
__global__ void __launch_bounds__(256)
gather_kernel(const __half* __restrict__ hh,const float* __restrict__ deg,
              const int* __restrict__ base,const int* __restrict__ cnt,
              const float2* __restrict__ edges,float* __restrict__ out,int n)
{
    int node=blockIdx.x*(blockDim.x>>5)+(threadIdx.x>>5);
    if(node>=n) return;
    int lane=threadIdx.x&31,sub=lane>>4,l16=lane&15;

    float acc[8]={0,0,0,0,0,0,0,0};
    if(sub==0){
        uint4 u=__ldg((const uint4*)(hh+(size_t)node*128)+l16);
        float4 a=h4(make_uint2(u.x,u.y)),b=h4(make_uint2(u.z,u.w));
        acc[0]=a.x;acc[1]=a.y;acc[2]=a.z;acc[3]=a.w;
        acc[4]=b.x;acc[5]=b.y;acc[6]=b.z;acc[7]=b.w;
    }

    int s=__ldg(base+node);
    int end=s+__ldg(cnt+node);
    for(;s<end;s+=4){
        int ia=s+sub,ib=s+2+sub;
        float2 r0=(ia<end)?__ldg(edges+ia):make_float2(0.f,0.f);
        float2 r1=(ib<end)?__ldg(edges+ib):make_float2(0.f,0.f);
        int row0=(ia<end)?__float_as_int(r0.x):0;
        int row1=(ib<end)?__float_as_int(r1.x):0;
        uint4 u0=__ldg((const uint4*)(hh+(size_t)row0*128)+l16);
        uint4 u1=__ldg((const uint4*)(hh+(size_t)row1*128)+l16);
        float4 a0=h4(make_uint2(u0.x,u0.y)),b0=h4(make_uint2(u0.z,u0.w));
        float4 a1=h4(make_uint2(u1.x,u1.y)),b1=h4(make_uint2(u1.z,u1.w));
        float g0=r0.y,g1=r1.y;
        acc[0]=fmaf(g0,a0.x,acc[0]);acc[1]=fmaf(g0,a0.y,acc[1]);
        acc[2]=fmaf(g0,a0.z,acc[2]);acc[3]=fmaf(g0,a0.w,acc[3]);
        acc[4]=fmaf(g0,b0.x,acc[4]);acc[5]=fmaf(g0,b0.y,acc[5]);
        acc[6]=fmaf(g0,b0.z,acc[6]);acc[7]=fmaf(g0,b0.w,acc[7]);
        acc[0]=fmaf(g1,a1.x,acc[0]);acc[1]=fmaf(g1,a1.y,acc[1]);
        acc[2]=fmaf(g1,a1.z,acc[2]);acc[3]=fmaf(g1,a1.w,acc[3]);
        acc[4]=fmaf(g1,b1.x,acc[4]);acc[5]=fmaf(g1,b1.y,acc[5]);
        acc[6]=fmaf(g1,b1.z,acc[6]);acc[7]=fmaf(g1,b1.w,acc[7]);
    }

    float di=rsqrtf(__ldg(deg+node));
    #pragma unroll
    for(int j=0;j<8;j++){
        acc[j]+=__shfl_xor_sync(0xffffffffu,acc[j],16);
        acc[j]*=di;
    }
    if(sub==0){
        float* o=out+(size_t)node*128+l16*8;
        *(float4*)(o)  =make_float4(acc[0],acc[1],acc[2],acc[3]);
        *(float4*)(o+4)=make_float4(acc[4],acc[5],acc[6],acc[7]);
    }
}

extern "C" void kernel_launch(void* const* d_in,const int* in_sizes,int n_in,
                              void* d_out,int out_size)
{
    const float* x=(const float*)d_in[0];
    const int*   ei=(const int*)d_in[1];
    const float* ea=(const float*)d_in[2];
    const float* W1=(const float*)d_in[3];
    const float* m1w1=(const float*)d_in[4];
    const float* m1b1=(const float*)d_in[5];
    const float* m1w2=(const float*)d_in[6];
    const float* m1b2=(const float*)d_in[7];
    const float* W2=(const float*)d_in[8];
    const float* m2w1=(const float*)d_in[9];
    const float* m2b1=(const float*)d_in[10];
    const float* m2w2=(const float*)d_in[11];
    const float* m2b2=(const float*)d_in[12];
    float* out=(float*)d_out;

    int n=in_sizes[0]/128;
    int E=in_sizes[1]/2;
    const int* rows=ei;
    const int* cols=ei+E;
    int nblk=(n+1023)/1024;

    float *pagg,*pd1,*pd2;
    __half* phh;
    float2 *pe1,*pe2;
    int *pcnt,*pcur,*pbase,*pbsums;
    cudaGetSymbolAddress((void**)&phh,g_hh);
    cudaGetSymbolAddress((void**)&pagg,g_agg);
    cudaGetSymbolAddress((void**)&pd1,g_d1);
    cudaGetSymbolAddress((void**)&pd2,g_d2);
    cudaGetSymbolAddress((void**)&pcnt,g_cnt);
    cudaGetSymbolAddress((void**)&pcur,g_cur);
    cudaGetSymbolAddress((void**)&pbase,g_base);
    cudaGetSymbolAddress((void**)&pbsums,g_bsums);
    cudaGetSymbolAddress((void**)&pe1,g_e1);
    cudaGetSymbolAddress((void**)&pe2,g_e2);

    const int GATE_SMEM=4864*4;                  // 19456 B
    const int GEMM_SMEM=(17408+16*16*132)*4;     // 204800 B
    cudaFuncSetAttribute(gate_mma_kernel,cudaFuncAttributeMaxDynamicSharedMemorySize,GATE_SMEM);
    cudaFuncSetAttribute(gemm_mma_kernel,cudaFuncAttributeMaxDynamicSharedMemorySize,GEMM_SMEM);

    zero_cnt_kernel<<<(n+255)/256,256>>>(pcnt,n);
    hist_kernel<<<((E+3)/4+255)/256,256>>>(cols,pcnt,E);
    scan_block_sums<<<nblk,1024>>>(pcnt,pbsums,n);
    scan_final<<<nblk,1024>>>(pcnt,pbsums,pbase,pd1,pd2,pcur,n);

    gate_mma_kernel<<<592,256,GATE_SMEM>>>(ea,m1w1,m1b1,m1w2,m1b2,m2w1,m2b1,m2w2,m2b2,
                                           rows,cols,pbase,pcur,pe1,pe2,pd1,pd2,E);

    gemm_mma_kernel<<<148,512,GEMM_SMEM>>>(x,W1,pd1,phh,n,0);
    gather_kernel<<<(n+7)/8,256>>>(phh,pd1,pbase,pcnt,pe1,pagg,n);

    gemm_mma_kernel<<<148,512,GEMM_SMEM>>>(pagg,W2,pd2,phh,n,1);
    gather_kernel<<<(n+7)/8,256>>>(phh,pd2,pbase,pcnt,pe2,out,n);
}